// round 12
// baseline (speedup 1.0000x reference)
#include <cuda_runtime.h>
#include <cuda_fp16.h>
#include <cstdint>

#define DEV_INLINE __device__ __forceinline__

constexpr int Bn = 1024, Tn = 128, In = 128, Hn = 1024, G4 = 4096, On = 64;
constexpr int K_TOT = In + Hn;          // 1152
constexpr int KC = 128;                 // K halves per chunk
constexpr int NCH = Hn / KC;            // 8 h-chunks per step (consumer)
constexpr int MT = 128, HT = 64;
constexpr int WPAD = 68, ROWB = WPAD * 4;   // 272B padded rows
constexpr int NCON = 128;               // consumer CTAs (tiles)
constexpr int NPROD = 20;               // producer CTAs on spare SMs
constexpr int NBLK = NCON + NPROD;      // 148
constexpr int RING = 4;                 // xg ring depth (slots)

__device__ __half g_h0[Bn * Hn];
__device__ __half g_h1[Bn * Hn];
__device__ float  g_c[Bn * Hn];
__device__ __half g_w[G4 * K_TOT];      // [w_ih | w_hh] fp16
__device__ __half g_x[Bn * Tn * In];
__device__ float  g_xg[(size_t)RING * NCON * 256 * 128];  // xg ring, fragment layout, 67MB
__device__ int    g_xg_flag[RING * NCON];                 // holds t+1 when tile ready
__device__ int    g_step;                                 // consumer progress (steps done)
__device__ unsigned g_bar_ctr = 0;
__device__ unsigned g_bar_sense = 0;

constexpr int SM_STG0 = 1024;
constexpr int A_BYTES = MT * ROWB;                  // 34816
constexpr int B_BYTES = 4 * HT * ROWB;              // 69632
constexpr int STG_BYTES = A_BYTES + B_BYTES;        // 104448
constexpr int SMEM_BYTES = SM_STG0 + 2 * STG_BYTES; // 209920

#define CPA16(dst, src) asm volatile("cp.async.cg.shared.global [%0], [%1], 16;" :: "r"(dst), "l"(src))
#define CP_COMMIT()     asm volatile("cp.async.commit_group;" ::: "memory")
#define CP_WAIT_0()     asm volatile("cp.async.wait_group 0;" ::: "memory")

DEV_INLINE uint32_t smem_u32(const void* p) {
    uint32_t a;
    asm("{ .reg .u64 t; cvta.to.shared.u64 t, %1; cvt.u32.u64 %0, t; }" : "=r"(a) : "l"(p));
    return a;
}
DEV_INLINE void ldsm4(uint32_t& r0, uint32_t& r1, uint32_t& r2, uint32_t& r3, uint32_t addr) {
    asm volatile("ldmatrix.sync.aligned.m8n8.x4.shared.b16 {%0,%1,%2,%3}, [%4];"
                 : "=r"(r0), "=r"(r1), "=r"(r2), "=r"(r3) : "r"(addr));
}
DEV_INLINE void mma16(float* c, const uint32_t* a, const uint32_t* b) {
    asm volatile(
        "mma.sync.aligned.m16n8k16.row.col.f32.f16.f16.f32 "
        "{%0,%1,%2,%3}, {%4,%5,%6,%7}, {%8,%9}, {%0,%1,%2,%3};"
        : "+f"(c[0]), "+f"(c[1]), "+f"(c[2]), "+f"(c[3])
        : "r"(a[0]), "r"(a[1]), "r"(a[2]), "r"(a[3]), "r"(b[0]), "r"(b[1]));
}
DEV_INLINE float sigf(float x) {
    float e, r;
    asm("ex2.approx.f32 %0, %1;" : "=f"(e) : "f"(-1.4426950408889634f * x));
    asm("rcp.approx.f32 %0, %1;" : "=f"(r) : "f"(1.0f + e));
    return r;
}
DEV_INLINE float tanhf_(float x) { return 2.0f * sigf(2.0f * x) - 1.0f; }

// ---------------- prep ----------------
__global__ void init_hc_kernel() {
    int i = blockIdx.x * blockDim.x + threadIdx.x;
    if (i < Bn * Hn) {
        g_h0[i] = __float2half(0.0f);
        g_h1[i] = __float2half(0.0f);
        g_c[i] = 0.0f;
    }
    if (i < RING * NCON) g_xg_flag[i] = 0;
    if (i == 0) { g_bar_ctr = 0; g_bar_sense = 0; g_step = 0; }
}
__global__ void prep_w_kernel(const float* __restrict__ w_ih, const float* __restrict__ w_hh) {
    int i = blockIdx.x * blockDim.x + threadIdx.x;
    if (i >= G4 * K_TOT) return;
    int n = i / K_TOT, k = i - n * K_TOT;
    g_w[i] = __float2half_rn(k < In ? w_ih[n * In + k] : w_hh[n * Hn + (k - In)]);
}
__global__ void prep_x_kernel(const float* __restrict__ x) {
    int i = blockIdx.x * blockDim.x + threadIdx.x;
    if (i < Bn * Tn * In) g_x[i] = __float2half_rn(x[i]);
}

// ---------------- tile loader: A 128x128h (from abase), B 256x128h (gathered w) ----------------
DEV_INLINE void load_tile(uint32_t sA, uint32_t sB, const __half* abase, int apitch,
                          const __half* wbase, int nbase, int tid) {
#pragma unroll
    for (int j = 0; j < 8; j++) {
        int op = j * 256 + tid, row = op >> 4, seg = op & 15;
        CPA16(sA + row * ROWB + seg * 16, abase + (size_t)row * apitch + seg * 8);
    }
#pragma unroll
    for (int j = 0; j < 16; j++) {
        int op = j * 256 + tid, rb = op >> 4, seg = op & 15;
        int n = ((rb >> 6) << 10) + nbase + (rb & 63);
        CPA16(sB + rb * ROWB + seg * 16, wbase + (size_t)n * K_TOT + seg * 8);
    }
}

// ---------------- one K=128 chunk of MMAs (ldmatrix + frag double-buffer) ----------------
DEV_INLINE void mma_chunk(float (&acc)[4][8][4], uint32_t aA, uint32_t bA) {
    uint32_t aq[2][4][4], bq[2][8][2];
#pragma unroll
    for (int mt = 0; mt < 4; mt++)
        ldsm4(aq[0][mt][0], aq[0][mt][1], aq[0][mt][2], aq[0][mt][3], aA + mt * (16 * ROWB));
#pragma unroll
    for (int s = 0; s < 4; s++)
        ldsm4(bq[0][2 * s][0], bq[0][2 * s][1], bq[0][2 * s + 1][0], bq[0][2 * s + 1][1],
              bA + s * (64 * ROWB));
#pragma unroll
    for (int ks = 0; ks < 8; ks++) {
        int cb = ks & 1, nb = cb ^ 1;
        if (ks < 7) {
            uint32_t ko = (uint32_t)((ks + 1) * 32);
#pragma unroll
            for (int mt = 0; mt < 4; mt++)
                ldsm4(aq[nb][mt][0], aq[nb][mt][1], aq[nb][mt][2], aq[nb][mt][3],
                      aA + mt * (16 * ROWB) + ko);
#pragma unroll
            for (int s = 0; s < 4; s++)
                ldsm4(bq[nb][2 * s][0], bq[nb][2 * s][1], bq[nb][2 * s + 1][0], bq[nb][2 * s + 1][1],
                      bA + s * (64 * ROWB) + ko);
        }
#pragma unroll
        for (int mt = 0; mt < 4; mt++)
#pragma unroll
            for (int j = 0; j < 8; j++)
                mma16(acc[mt][j], aq[cb][mt], bq[cb][j]);
    }
}

// ---------------- persistent kernel: 128 consumers + 20 producers ----------------
__global__ void __launch_bounds__(256, 1)
lstm_persistent_kernel(const float* __restrict__ b_ih, const float* __restrict__ b_hh) {
    extern __shared__ char smem[];
    uint32_t sb = smem_u32(smem);
    int bid = blockIdx.x;
    int tid = threadIdx.x, wid = tid >> 5, lid = tid & 31;
    int wm = wid >> 2, wn = wid & 3;
    int g = lid >> 2, tg = lid & 3;

    int mrow = ((lid >> 3) & 1) * 8 + (lid & 7);
    uint32_t aoff = (uint32_t)(mrow * ROWB + (lid >> 4) * 16);
    uint32_t boff = (uint32_t)(((lid >> 4) * 8 + (lid & 7)) * ROWB + ((lid >> 3) & 1) * 16);

    uint32_t stgA[2], stgB[2];
#pragma unroll
    for (int s = 0; s < 2; s++) {
        stgA[s] = sb + SM_STG0 + s * STG_BYTES;
        stgB[s] = stgA[s] + A_BYTES;
    }

    if (bid >= NCON) {
        // ================= PRODUCER =================
        int pid = bid - NCON;
        int t = 0, tile = pid, s = 0;
        {
            int m0 = (tile & 7) * MT, nbase = (tile >> 3) * HT;
            load_tile(stgA[0], stgB[0], g_x + (size_t)m0 * (Tn * In), Tn * In, g_w, nbase, tid);
            CP_COMMIT();
        }
        while (true) {
            int nt = t, ntile = tile + NPROD;
            if (ntile >= NCON) { nt = t + 1; ntile = pid; }
            bool have_next = nt < Tn;

            CP_WAIT_0();
            __syncthreads();                     // current tile visible; s^1 free
            if (have_next) {
                int nm0 = (ntile & 7) * MT, nnb = (ntile >> 3) * HT;
                load_tile(stgA[s ^ 1], stgB[s ^ 1],
                          g_x + (size_t)nm0 * (Tn * In) + nt * In, Tn * In, g_w, nnb, tid);
            }
            CP_COMMIT();

            __align__(16) float acc[4][8][4];
#pragma unroll
            for (int mt = 0; mt < 4; mt++)
#pragma unroll
                for (int j = 0; j < 8; j++)
#pragma unroll
                    for (int q = 0; q < 4; q++) acc[mt][j][q] = 0.0f;

            mma_chunk(acc, stgA[s] + (uint32_t)(wm * 64 * ROWB) + aoff,
                           stgB[s] + (uint32_t)(wn * 16 * ROWB) + boff);

            // ring-slot reuse gate: consumers must be past step t-4
            if (tid == 0)
                while (*(volatile int*)&g_step < t - 3) __nanosleep(64);
            __syncthreads();

            float* dst = g_xg + ((size_t)(t & 3) * NCON + tile) * (256 * 128) + (size_t)tid * 128;
            const float4* af = (const float4*)&acc[0][0][0];
#pragma unroll
            for (int i = 0; i < 32; i++) ((float4*)dst)[i] = af[i];
            __threadfence();
            __syncthreads();                     // all stores fenced before flag
            if (tid == 0) atomicExch(&g_xg_flag[(t & 3) * NCON + tile], t + 1);

            if (!have_next) break;
            t = nt; tile = ntile; s ^= 1;
        }
        return;
    }

    // ================= CONSUMER =================
    int m0 = (bid & 7) * MT, nbase = (bid >> 3) * HT;

    {   // bias for 256 gathered gate cols (once)
        int n = ((tid >> 6) << 10) + nbase + (tid & 63);
        ((float*)smem)[tid] = b_ih[n] + b_hh[n];
    }
    __syncthreads();

    unsigned sense = 0;

#pragma unroll 1
    for (int t = 0; t < Tn; t++) {
        const __half* hin = (t & 1) ? g_h1 : g_h0;
        __half* hout      = (t & 1) ? g_h0 : g_h1;

        // h-chunk 0 load first (overlaps flag wait + xg loads)
        load_tile(stgA[0], stgB[0], hin + (size_t)m0 * Hn, Hn, g_w + In, nbase, tid);
        CP_COMMIT();

        // wait for my xg tile
        if (tid == 0)
            while (*(volatile int*)&g_xg_flag[(t & 3) * NCON + bid] != t + 1) __nanosleep(32);
        __syncthreads();
        __threadfence();

        // acc init from xg ring (L1-bypassing loads)
        __align__(16) float acc[4][8][4];
        {
            const float4* src = (const float4*)(g_xg +
                ((size_t)(t & 3) * NCON + bid) * (256 * 128) + (size_t)tid * 128);
            float4* af = (float4*)&acc[0][0][0];
#pragma unroll
            for (int i = 0; i < 32; i++) af[i] = __ldcg(src + i);
        }

#pragma unroll 1
        for (int kc = 0; kc < NCH; kc++) {
            CP_WAIT_0();
            __syncthreads();
            if (kc + 1 < NCH)
                load_tile(stgA[(kc + 1) & 1], stgB[(kc + 1) & 1],
                          hin + (size_t)m0 * Hn + (kc + 1) * KC, Hn,
                          g_w + In + (kc + 1) * KC, nbase, tid);
            CP_COMMIT();
            mma_chunk(acc, stgA[kc & 1] + (uint32_t)(wm * 64 * ROWB) + aoff,
                           stgB[kc & 1] + (uint32_t)(wn * 16 * ROWB) + boff);
        }

        // epilogue
        const float* bsm = (const float*)smem;
#pragma unroll
        for (int mt = 0; mt < 4; mt++) {
            int rbase = m0 + wm * 64 + mt * 16 + g;
#pragma unroll
            for (int sub = 0; sub < 2; sub++) {
                int hc = wn * 16 + sub * 8 + 2 * tg;
                float bi0 = bsm[hc],        bi1 = bsm[hc + 1];
                float bf0 = bsm[64 + hc],   bf1 = bsm[64 + hc + 1];
                float bg0 = bsm[128 + hc],  bg1 = bsm[128 + hc + 1];
                float bo0 = bsm[192 + hc],  bo1 = bsm[192 + hc + 1];
#pragma unroll
                for (int rr = 0; rr < 2; rr++) {
                    int r = rbase + rr * 8;
                    size_t off = (size_t)r * Hn + nbase + hc;
                    float2 co = *(const float2*)(g_c + off);
                    int q0 = rr * 2, q1 = rr * 2 + 1;
                    float i0 = acc[mt][0 + sub][q0] + bi0, i1 = acc[mt][0 + sub][q1] + bi1;
                    float f0 = acc[mt][2 + sub][q0] + bf0, f1 = acc[mt][2 + sub][q1] + bf1;
                    float gg0 = acc[mt][4 + sub][q0] + bg0, gg1 = acc[mt][4 + sub][q1] + bg1;
                    float o0 = acc[mt][6 + sub][q0] + bo0, o1 = acc[mt][6 + sub][q1] + bo1;
                    float cn0 = sigf(f0) * co.x + sigf(i0) * tanhf_(gg0);
                    float cn1 = sigf(f1) * co.y + sigf(i1) * tanhf_(gg1);
                    *(float2*)(g_c + off) = make_float2(cn0, cn1);
                    __half2 hv = __floats2half2_rn(sigf(o0) * tanhf_(cn0),
                                                   sigf(o1) * tanhf_(cn1));
                    *(__half2*)(hout + off) = hv;
                }
            }
        }

        // grid barrier among the 128 consumers; master publishes g_step
        __threadfence();
        __syncthreads();
        if (tid == 0) {
            sense ^= 1u;
            unsigned pos = atomicAdd(&g_bar_ctr, 1u);
            if (pos == NCON - 1) {
                atomicExch(&g_bar_ctr, 0u);
                *(volatile int*)&g_step = t + 1;
                __threadfence();
                atomicExch(&g_bar_sense, sense);
            } else {
                volatile unsigned* vs = &g_bar_sense;
                while (*vs != sense) __nanosleep(32);
                __threadfence();
            }
        }
        __syncthreads();
    }
}

// ---------------- final FC (t=127 odd -> final h in g_h0) ----------------
__global__ void fc_kernel(const float* __restrict__ w_fc, const float* __restrict__ b_fc,
                          float* __restrict__ out) {
    __shared__ float hs[Hn];
    int b = blockIdx.x;
    const __half2* hsrc = (const __half2*)(g_h0 + (size_t)b * Hn);
    for (int i = threadIdx.x; i < Hn / 2; i += 64) {
        float2 v = __half22float2(hsrc[i]);
        hs[2 * i] = v.x; hs[2 * i + 1] = v.y;
    }
    __syncthreads();
    int o = threadIdx.x;
    const float4* wr = (const float4*)(w_fc + (size_t)o * Hn);
    float acc = 0.0f;
#pragma unroll 8
    for (int k = 0; k < Hn / 4; k++) {
        float4 w4 = wr[k];
        float4 h4 = ((const float4*)hs)[k];
        acc += w4.x * h4.x + w4.y * h4.y + w4.z * h4.z + w4.w * h4.w;
    }
    out[b * On + o] = acc + b_fc[o];
}

extern "C" void kernel_launch(void* const* d_in, const int* in_sizes, int n_in,
                              void* d_out, int out_size) {
    (void)in_sizes; (void)n_in; (void)out_size;
    const float* x    = (const float*)d_in[0];
    const float* w_ih = (const float*)d_in[1];
    const float* w_hh = (const float*)d_in[2];
    const float* b_ih = (const float*)d_in[3];
    const float* b_hh = (const float*)d_in[4];
    const float* w_fc = (const float*)d_in[5];
    const float* b_fc = (const float*)d_in[6];
    float* out = (float*)d_out;

    cudaFuncSetAttribute(lstm_persistent_kernel,
                         cudaFuncAttributeMaxDynamicSharedMemorySize, SMEM_BYTES);

    init_hc_kernel<<<(Bn * Hn) / 256, 256>>>();
    prep_w_kernel<<<(G4 * K_TOT + 255) / 256, 256>>>(w_ih, w_hh);
    prep_x_kernel<<<(Bn * Tn * In) / 256, 256>>>(x);

    lstm_persistent_kernel<<<NBLK, 256, SMEM_BYTES>>>(b_ih, b_hh);

    fc_kernel<<<Bn, 64>>>(w_fc, b_fc, out);
}

// round 13
// speedup vs baseline: 1.6323x; 1.6323x over previous
#include <cuda_runtime.h>
#include <cuda_fp16.h>
#include <cstdint>

#define DEV_INLINE __device__ __forceinline__

constexpr int Bn = 1024, Tn = 128, In = 128, Hn = 1024, G4 = 4096, On = 64;
constexpr int K_TOT = In + Hn;          // 1152
constexpr int KC = 128;                 // K halves per chunk
constexpr int NCH = Hn / KC;            // 8 h-chunks per step (consumer)
constexpr int MT = 128, HT = 64;
constexpr int WPAD = 68, ROWB = WPAD * 4;   // 272B padded rows
constexpr int NCON = 128;               // consumer CTAs (tiles)
constexpr int NPROD = 20;               // producer CTAs on spare SMs
constexpr int NBLK = NCON + NPROD;      // 148
constexpr int RING = 4;                 // xg ring depth
constexpr int TILE_F = 256 * 128;       // floats per xg tile (32768)

__device__ __half g_h0[Bn * Hn];
__device__ __half g_h1[Bn * Hn];
__device__ float  g_c[Bn * Hn];
__device__ __half g_w[G4 * K_TOT];      // [w_ih | w_hh] fp16
__device__ __half g_x[Bn * Tn * In];
__device__ float  g_xg[(size_t)RING * NCON * TILE_F];  // xg ring (tid-major float4 layout)
__device__ int    g_xg_flag[RING * NCON];              // holds t+1 when tile ready
__device__ int    g_step;                              // consumer steps completed
__device__ unsigned g_bar_ctr = 0;
__device__ unsigned g_bar_sense = 0;

constexpr int SM_STG0 = 1024;
constexpr int A_BYTES = MT * ROWB;                  // 34816
constexpr int B_BYTES = 4 * HT * ROWB;              // 69632
constexpr int STG_BYTES = A_BYTES + B_BYTES;        // 104448
constexpr int SMEM_BYTES = SM_STG0 + 2 * STG_BYTES; // 209920

#define CPA16(dst, src) asm volatile("cp.async.cg.shared.global [%0], [%1], 16;" :: "r"(dst), "l"(src))
#define CP_COMMIT()     asm volatile("cp.async.commit_group;" ::: "memory")
#define CP_WAIT_0()     asm volatile("cp.async.wait_group 0;" ::: "memory")

DEV_INLINE uint32_t smem_u32(const void* p) {
    uint32_t a;
    asm("{ .reg .u64 t; cvta.to.shared.u64 t, %1; cvt.u32.u64 %0, t; }" : "=r"(a) : "l"(p));
    return a;
}
DEV_INLINE void ldsm4(uint32_t& r0, uint32_t& r1, uint32_t& r2, uint32_t& r3, uint32_t addr) {
    asm volatile("ldmatrix.sync.aligned.m8n8.x4.shared.b16 {%0,%1,%2,%3}, [%4];"
                 : "=r"(r0), "=r"(r1), "=r"(r2), "=r"(r3) : "r"(addr));
}
DEV_INLINE void mma16(float* c, const uint32_t* a, const uint32_t* b) {
    asm volatile(
        "mma.sync.aligned.m16n8k16.row.col.f32.f16.f16.f32 "
        "{%0,%1,%2,%3}, {%4,%5,%6,%7}, {%8,%9}, {%0,%1,%2,%3};"
        : "+f"(c[0]), "+f"(c[1]), "+f"(c[2]), "+f"(c[3])
        : "r"(a[0]), "r"(a[1]), "r"(a[2]), "r"(a[3]), "r"(b[0]), "r"(b[1]));
}
DEV_INLINE float sigf(float x) {
    float e, r;
    asm("ex2.approx.f32 %0, %1;" : "=f"(e) : "f"(-1.4426950408889634f * x));
    asm("rcp.approx.f32 %0, %1;" : "=f"(r) : "f"(1.0f + e));
    return r;
}
DEV_INLINE float tanhf_(float x) { return 2.0f * sigf(2.0f * x) - 1.0f; }

// ---------------- prep ----------------
__global__ void init_hc_kernel() {
    int i = blockIdx.x * blockDim.x + threadIdx.x;
    if (i < Bn * Hn) {
        g_h0[i] = __float2half(0.0f);
        g_h1[i] = __float2half(0.0f);
        g_c[i] = 0.0f;
    }
    if (i < RING * NCON) g_xg_flag[i] = 0;
    if (i == 0) { g_bar_ctr = 0; g_bar_sense = 0; g_step = 0; }
}
__global__ void prep_w_kernel(const float* __restrict__ w_ih, const float* __restrict__ w_hh) {
    int i = blockIdx.x * blockDim.x + threadIdx.x;
    if (i >= G4 * K_TOT) return;
    int n = i / K_TOT, k = i - n * K_TOT;
    g_w[i] = __float2half_rn(k < In ? w_ih[n * In + k] : w_hh[n * Hn + (k - In)]);
}
__global__ void prep_x_kernel(const float* __restrict__ x) {
    int i = blockIdx.x * blockDim.x + threadIdx.x;
    if (i < Bn * Tn * In) g_x[i] = __float2half_rn(x[i]);
}

// ---------------- tile loader ----------------
DEV_INLINE void load_tile(uint32_t sA, uint32_t sB, const __half* abase, int apitch,
                          const __half* wbase, int nbase, int tid) {
#pragma unroll
    for (int j = 0; j < 8; j++) {
        int op = j * 256 + tid, row = op >> 4, seg = op & 15;
        CPA16(sA + row * ROWB + seg * 16, abase + (size_t)row * apitch + seg * 8);
    }
#pragma unroll
    for (int j = 0; j < 16; j++) {
        int op = j * 256 + tid, rb = op >> 4, seg = op & 15;
        int n = ((rb >> 6) << 10) + nbase + (rb & 63);
        CPA16(sB + rb * ROWB + seg * 16, wbase + (size_t)n * K_TOT + seg * 8);
    }
}

// ---------------- one K=128 chunk of MMAs ----------------
DEV_INLINE void mma_chunk(float (&acc)[4][8][4], uint32_t aA, uint32_t bA) {
    uint32_t aq[2][4][4], bq[2][8][2];
#pragma unroll
    for (int mt = 0; mt < 4; mt++)
        ldsm4(aq[0][mt][0], aq[0][mt][1], aq[0][mt][2], aq[0][mt][3], aA + mt * (16 * ROWB));
#pragma unroll
    for (int s = 0; s < 4; s++)
        ldsm4(bq[0][2 * s][0], bq[0][2 * s][1], bq[0][2 * s + 1][0], bq[0][2 * s + 1][1],
              bA + s * (64 * ROWB));
#pragma unroll
    for (int ks = 0; ks < 8; ks++) {
        int cb = ks & 1, nb = cb ^ 1;
        if (ks < 7) {
            uint32_t ko = (uint32_t)((ks + 1) * 32);
#pragma unroll
            for (int mt = 0; mt < 4; mt++)
                ldsm4(aq[nb][mt][0], aq[nb][mt][1], aq[nb][mt][2], aq[nb][mt][3],
                      aA + mt * (16 * ROWB) + ko);
#pragma unroll
            for (int s = 0; s < 4; s++)
                ldsm4(bq[nb][2 * s][0], bq[nb][2 * s][1], bq[nb][2 * s + 1][0], bq[nb][2 * s + 1][1],
                      bA + s * (64 * ROWB) + ko);
        }
#pragma unroll
        for (int mt = 0; mt < 4; mt++)
#pragma unroll
            for (int j = 0; j < 8; j++)
                mma16(acc[mt][j], aq[cb][mt], bq[cb][j]);
    }
}

// ---------------- persistent kernel: 128 consumers + 20 producers ----------------
__global__ void __launch_bounds__(256, 1)
lstm_persistent_kernel(const float* __restrict__ b_ih, const float* __restrict__ b_hh) {
    extern __shared__ char smem[];
    uint32_t sb = smem_u32(smem);
    int bid = blockIdx.x;
    int tid = threadIdx.x, wid = tid >> 5, lid = tid & 31;
    int wm = wid >> 2, wn = wid & 3;
    int g = lid >> 2, tg = lid & 3;

    int mrow = ((lid >> 3) & 1) * 8 + (lid & 7);
    uint32_t aoff = (uint32_t)(mrow * ROWB + (lid >> 4) * 16);
    uint32_t boff = (uint32_t)(((lid >> 4) * 8 + (lid & 7)) * ROWB + ((lid >> 3) & 1) * 16);

    uint32_t stgA[2], stgB[2];
#pragma unroll
    for (int s = 0; s < 2; s++) {
        stgA[s] = sb + SM_STG0 + s * STG_BYTES;
        stgB[s] = stgA[s] + A_BYTES;
    }

    if (bid >= NCON) {
        // ================= PRODUCER (xg tiles, 3-4 steps ahead) =================
        int pid = bid - NCON;
        int t = 0, tile = pid, s = 0;
        {
            int m0 = (tile & 7) * MT, nbase = (tile >> 3) * HT;
            load_tile(stgA[0], stgB[0], g_x + (size_t)m0 * (Tn * In), Tn * In, g_w, nbase, tid);
            CP_COMMIT();
        }
        while (true) {
            int nt = t, ntile = tile + NPROD;
            if (ntile >= NCON) { nt = t + 1; ntile = pid; }
            bool have_next = nt < Tn;

            CP_WAIT_0();
            __syncthreads();
            if (have_next) {
                int nm0 = (ntile & 7) * MT, nnb = (ntile >> 3) * HT;
                load_tile(stgA[s ^ 1], stgB[s ^ 1],
                          g_x + (size_t)nm0 * (Tn * In) + nt * In, Tn * In, g_w, nnb, tid);
            }
            CP_COMMIT();

            __align__(16) float acc[4][8][4];
#pragma unroll
            for (int mt = 0; mt < 4; mt++)
#pragma unroll
                for (int j = 0; j < 8; j++)
#pragma unroll
                    for (int q = 0; q < 4; q++) acc[mt][j][q] = 0.0f;

            mma_chunk(acc, stgA[s] + (uint32_t)(wm * 64 * ROWB) + aoff,
                           stgB[s] + (uint32_t)(wn * 16 * ROWB) + boff);

            if (tid == 0)
                while (*(volatile int*)&g_step < t - 3) __nanosleep(64);
            __syncthreads();

            // COALESCED ring store: tid-major float4 (warp writes 512B contiguous)
            float4* slot4 = (float4*)(g_xg + ((size_t)(t & 3) * NCON + tile) * TILE_F);
            const float4* af = (const float4*)&acc[0][0][0];
#pragma unroll
            for (int i = 0; i < 32; i++) slot4[i * 256 + tid] = af[i];
            __threadfence();
            __syncthreads();
            if (tid == 0) atomicExch(&g_xg_flag[(t & 3) * NCON + tile], t + 1);

            if (!have_next) break;
            t = nt; tile = ntile; s ^= 1;
        }
        return;
    }

    // ================= CONSUMER (h-GEMM, K=1024, 8 chunks) =================
    int m0 = (bid & 7) * MT, nbase = (bid >> 3) * HT;

    {   // bias for 256 gathered gate cols (once)
        int n = ((tid >> 6) << 10) + nbase + (tid & 63);
        ((float*)smem)[tid] = b_ih[n] + b_hh[n];
    }
    __syncthreads();

    unsigned sense = 0;

#pragma unroll 1
    for (int t = 0; t < Tn; t++) {
        const __half* hin = (t & 1) ? g_h1 : g_h0;
        __half* hout      = (t & 1) ? g_h0 : g_h1;

        load_tile(stgA[0], stgB[0], hin + (size_t)m0 * Hn, Hn, g_w + In, nbase, tid);
        CP_COMMIT();

        if (tid == 0)
            while (*(volatile int*)&g_xg_flag[(t & 3) * NCON + bid] != t + 1) __nanosleep(32);
        __syncthreads();
        __threadfence();

        // COALESCED acc init from ring
        __align__(16) float acc[4][8][4];
        {
            const float4* slot4 = (const float4*)(g_xg +
                ((size_t)(t & 3) * NCON + bid) * TILE_F);
            float4* af = (float4*)&acc[0][0][0];
#pragma unroll
            for (int i = 0; i < 32; i++) af[i] = __ldcg(slot4 + i * 256 + tid);
        }

#pragma unroll 1
        for (int kc = 0; kc < NCH; kc++) {
            CP_WAIT_0();
            __syncthreads();
            if (kc + 1 < NCH)
                load_tile(stgA[(kc + 1) & 1], stgB[(kc + 1) & 1],
                          hin + (size_t)m0 * Hn + (kc + 1) * KC, Hn,
                          g_w + In + (kc + 1) * KC, nbase, tid);
            CP_COMMIT();
            mma_chunk(acc, stgA[kc & 1] + (uint32_t)(wm * 64 * ROWB) + aoff,
                           stgB[kc & 1] + (uint32_t)(wn * 16 * ROWB) + boff);
        }

        // epilogue
        const float* bsm = (const float*)smem;
#pragma unroll
        for (int mt = 0; mt < 4; mt++) {
            int rbase = m0 + wm * 64 + mt * 16 + g;
#pragma unroll
            for (int sub = 0; sub < 2; sub++) {
                int hc = wn * 16 + sub * 8 + 2 * tg;
                float bi0 = bsm[hc],        bi1 = bsm[hc + 1];
                float bf0 = bsm[64 + hc],   bf1 = bsm[64 + hc + 1];
                float bg0 = bsm[128 + hc],  bg1 = bsm[128 + hc + 1];
                float bo0 = bsm[192 + hc],  bo1 = bsm[192 + hc + 1];
#pragma unroll
                for (int rr = 0; rr < 2; rr++) {
                    int r = rbase + rr * 8;
                    size_t off = (size_t)r * Hn + nbase + hc;
                    float2 co = *(const float2*)(g_c + off);
                    int q0 = rr * 2, q1 = rr * 2 + 1;
                    float i0 = acc[mt][0 + sub][q0] + bi0, i1 = acc[mt][0 + sub][q1] + bi1;
                    float f0 = acc[mt][2 + sub][q0] + bf0, f1 = acc[mt][2 + sub][q1] + bf1;
                    float gg0 = acc[mt][4 + sub][q0] + bg0, gg1 = acc[mt][4 + sub][q1] + bg1;
                    float o0 = acc[mt][6 + sub][q0] + bo0, o1 = acc[mt][6 + sub][q1] + bo1;
                    float cn0 = sigf(f0) * co.x + sigf(i0) * tanhf_(gg0);
                    float cn1 = sigf(f1) * co.y + sigf(i1) * tanhf_(gg1);
                    *(float2*)(g_c + off) = make_float2(cn0, cn1);
                    __half2 hv = __floats2half2_rn(sigf(o0) * tanhf_(cn0),
                                                   sigf(o1) * tanhf_(cn1));
                    *(__half2*)(hout + off) = hv;
                }
            }
        }

        // consumer grid barrier; master publishes g_step
        __threadfence();
        __syncthreads();
        if (tid == 0) {
            sense ^= 1u;
            unsigned pos = atomicAdd(&g_bar_ctr, 1u);
            if (pos == NCON - 1) {
                atomicExch(&g_bar_ctr, 0u);
                *(volatile int*)&g_step = t + 1;
                __threadfence();
                atomicExch(&g_bar_sense, sense);
            } else {
                volatile unsigned* vs = &g_bar_sense;
                while (*vs != sense) __nanosleep(32);
                __threadfence();
            }
        }
        __syncthreads();
    }
}

// ---------------- final FC (t=127 odd -> final h in g_h0) ----------------
__global__ void fc_kernel(const float* __restrict__ w_fc, const float* __restrict__ b_fc,
                          float* __restrict__ out) {
    __shared__ float hs[Hn];
    int b = blockIdx.x;
    const __half2* hsrc = (const __half2*)(g_h0 + (size_t)b * Hn);
    for (int i = threadIdx.x; i < Hn / 2; i += 64) {
        float2 v = __half22float2(hsrc[i]);
        hs[2 * i] = v.x; hs[2 * i + 1] = v.y;
    }
    __syncthreads();
    int o = threadIdx.x;
    const float4* wr = (const float4*)(w_fc + (size_t)o * Hn);
    float acc = 0.0f;
#pragma unroll 8
    for (int k = 0; k < Hn / 4; k++) {
        float4 w4 = wr[k];
        float4 h4 = ((const float4*)hs)[k];
        acc += w4.x * h4.x + w4.y * h4.y + w4.z * h4.z + w4.w * h4.w;
    }
    out[b * On + o] = acc + b_fc[o];
}

extern "C" void kernel_launch(void* const* d_in, const int* in_sizes, int n_in,
                              void* d_out, int out_size) {
    (void)in_sizes; (void)n_in; (void)out_size;
    const float* x    = (const float*)d_in[0];
    const float* w_ih = (const float*)d_in[1];
    const float* w_hh = (const float*)d_in[2];
    const float* b_ih = (const float*)d_in[3];
    const float* b_hh = (const float*)d_in[4];
    const float* w_fc = (const float*)d_in[5];
    const float* b_fc = (const float*)d_in[6];
    float* out = (float*)d_out;

    cudaFuncSetAttribute(lstm_persistent_kernel,
                         cudaFuncAttributeMaxDynamicSharedMemorySize, SMEM_BYTES);

    init_hc_kernel<<<(Bn * Hn) / 256, 256>>>();
    prep_w_kernel<<<(G4 * K_TOT + 255) / 256, 256>>>(w_ih, w_hh);
    prep_x_kernel<<<(Bn * Tn * In) / 256, 256>>>(x);

    lstm_persistent_kernel<<<NBLK, 256, SMEM_BYTES>>>(b_ih, b_hh);

    fc_kernel<<<Bn, 64>>>(w_fc, b_fc, out);
}

// round 17
// speedup vs baseline: 1.9984x; 1.2243x over previous
#include <cuda_runtime.h>
#include <cuda_fp16.h>
#include <cstdint>

#define DEV_INLINE __device__ __forceinline__

constexpr int Bn = 1024, Tn = 128, In = 128, Hn = 1024, G4 = 4096, On = 64;
constexpr int K_TOT = In + Hn;          // 1152
constexpr int KC = 128;                 // K halves per chunk
constexpr int NCHUNK = 9;               // chunk 0 = x, 1..8 = h
constexpr int MT = 128, HT = 64;
constexpr int WPAD = 68, ROWB = WPAD * 4;   // 272B padded rows
constexpr int NBLK = 148;               // persistent worker CTAs (1/SM)
constexpr int NCHAIN = Bn / MT;         // 8 independent M-chains
constexpr int NNB = Hn / HT;            // 16 N-tiles per chain-step
constexpr int NJOBS = Tn * NCHAIN * NNB;    // 16384

__device__ __half g_h0[Bn * Hn];
__device__ __half g_h1[Bn * Hn];
__device__ float  g_c[Bn * Hn];
__device__ __half g_w[G4 * K_TOT];      // [w_ih | w_hh] fp16
__device__ __half g_x[Bn * Tn * In];
__device__ int    g_ticket;
__device__ int    g_done[NCHAIN * Tn];  // per (chain, step): tiles completed (0..16)

constexpr int SM_STG0 = 1024;
constexpr int A_BYTES = MT * ROWB;                  // 34816
constexpr int B_BYTES = 4 * HT * ROWB;              // 69632
constexpr int STG_BYTES = A_BYTES + B_BYTES;        // 104448
constexpr int SMEM_BYTES = SM_STG0 + 2 * STG_BYTES; // 209920

#define CPA16(dst, src) asm volatile("cp.async.cg.shared.global [%0], [%1], 16;" :: "r"(dst), "l"(src))
#define CP_COMMIT()     asm volatile("cp.async.commit_group;" ::: "memory")
#define CP_WAIT_0()     asm volatile("cp.async.wait_group 0;" ::: "memory")

DEV_INLINE uint32_t smem_u32(const void* p) {
    uint32_t a;
    asm("{ .reg .u64 t; cvta.to.shared.u64 t, %1; cvt.u32.u64 %0, t; }" : "=r"(a) : "l"(p));
    return a;
}
DEV_INLINE void ldsm4(uint32_t& r0, uint32_t& r1, uint32_t& r2, uint32_t& r3, uint32_t addr) {
    asm volatile("ldmatrix.sync.aligned.m8n8.x4.shared.b16 {%0,%1,%2,%3}, [%4];"
                 : "=r"(r0), "=r"(r1), "=r"(r2), "=r"(r3) : "r"(addr));
}
DEV_INLINE void mma16(float* c, const uint32_t* a, const uint32_t* b) {
    asm volatile(
        "mma.sync.aligned.m16n8k16.row.col.f32.f16.f16.f32 "
        "{%0,%1,%2,%3}, {%4,%5,%6,%7}, {%8,%9}, {%0,%1,%2,%3};"
        : "+f"(c[0]), "+f"(c[1]), "+f"(c[2]), "+f"(c[3])
        : "r"(a[0]), "r"(a[1]), "r"(a[2]), "r"(a[3]), "r"(b[0]), "r"(b[1]));
}
DEV_INLINE float sigf(float x) {
    float e, r;
    asm("ex2.approx.f32 %0, %1;" : "=f"(e) : "f"(-1.4426950408889634f * x));
    asm("rcp.approx.f32 %0, %1;" : "=f"(r) : "f"(1.0f + e));
    return r;
}
DEV_INLINE float tanhf_(float x) { return 2.0f * sigf(2.0f * x) - 1.0f; }

// ---------------- prep ----------------
__global__ void init_hc_kernel() {
    int i = blockIdx.x * blockDim.x + threadIdx.x;
    if (i < Bn * Hn) {
        g_h0[i] = __float2half(0.0f);
        g_h1[i] = __float2half(0.0f);
        g_c[i] = 0.0f;
    }
    if (i < NCHAIN * Tn) g_done[i] = 0;
    if (i == 0) g_ticket = 0;
}
__global__ void prep_w_kernel(const float* __restrict__ w_ih, const float* __restrict__ w_hh) {
    int i = blockIdx.x * blockDim.x + threadIdx.x;
    if (i >= G4 * K_TOT) return;
    int n = i / K_TOT, k = i - n * K_TOT;
    g_w[i] = __float2half_rn(k < In ? w_ih[n * In + k] : w_hh[n * Hn + (k - In)]);
}
__global__ void prep_x_kernel(const float* __restrict__ x) {
    int i = blockIdx.x * blockDim.x + threadIdx.x;
    if (i < Bn * Tn * In) g_x[i] = __float2half_rn(x[i]);
}

// ---------------- tile loader (cp.async.cg: L2-coherent reads) ----------------
DEV_INLINE void load_tile(uint32_t sA, uint32_t sB, const __half* abase, int apitch,
                          const __half* wbase, int nbase, int tid) {
#pragma unroll
    for (int j = 0; j < 8; j++) {
        int op = j * 256 + tid, row = op >> 4, seg = op & 15;
        CPA16(sA + row * ROWB + seg * 16, abase + (size_t)row * apitch + seg * 8);
    }
#pragma unroll
    for (int j = 0; j < 16; j++) {
        int op = j * 256 + tid, rb = op >> 4, seg = op & 15;
        int n = ((rb >> 6) << 10) + nbase + (rb & 63);
        CPA16(sB + rb * ROWB + seg * 16, wbase + (size_t)n * K_TOT + seg * 8);
    }
}

// ---------------- one K=128 chunk of MMAs ----------------
DEV_INLINE void mma_chunk(float (&acc)[4][8][4], uint32_t aA, uint32_t bA) {
    uint32_t aq[2][4][4], bq[2][8][2];
#pragma unroll
    for (int mt = 0; mt < 4; mt++)
        ldsm4(aq[0][mt][0], aq[0][mt][1], aq[0][mt][2], aq[0][mt][3], aA + mt * (16 * ROWB));
#pragma unroll
    for (int s = 0; s < 4; s++)
        ldsm4(bq[0][2 * s][0], bq[0][2 * s][1], bq[0][2 * s + 1][0], bq[0][2 * s + 1][1],
              bA + s * (64 * ROWB));
#pragma unroll
    for (int ks = 0; ks < 8; ks++) {
        int cb = ks & 1, nb = cb ^ 1;
        if (ks < 7) {
            uint32_t ko = (uint32_t)((ks + 1) * 32);
#pragma unroll
            for (int mt = 0; mt < 4; mt++)
                ldsm4(aq[nb][mt][0], aq[nb][mt][1], aq[nb][mt][2], aq[nb][mt][3],
                      aA + mt * (16 * ROWB) + ko);
#pragma unroll
            for (int s = 0; s < 4; s++)
                ldsm4(bq[nb][2 * s][0], bq[nb][2 * s][1], bq[nb][2 * s + 1][0], bq[nb][2 * s + 1][1],
                      bA + s * (64 * ROWB) + ko);
        }
#pragma unroll
        for (int mt = 0; mt < 4; mt++)
#pragma unroll
            for (int j = 0; j < 8; j++)
                mma16(acc[mt][j], aq[cb][mt], bq[cb][j]);
    }
}

// ---------------- persistent work-stealing kernel ----------------
__global__ void __launch_bounds__(256, 1)
lstm_ws_kernel(const float* __restrict__ b_ih, const float* __restrict__ b_hh) {
    extern __shared__ char smem[];
    __shared__ int jslot;
    uint32_t sb = smem_u32(smem);
    int tid = threadIdx.x, wid = tid >> 5, lid = tid & 31;
    int wm = wid >> 2, wn = wid & 3;
    int g = lid >> 2, tg = lid & 3;

    int mrow = ((lid >> 3) & 1) * 8 + (lid & 7);
    uint32_t aoff = (uint32_t)(mrow * ROWB + (lid >> 4) * 16);
    uint32_t boff = (uint32_t)(((lid >> 4) * 8 + (lid & 7)) * ROWB + ((lid >> 3) & 1) * 16);

    uint32_t stgA[2], stgB[2];
#pragma unroll
    for (int s = 0; s < 2; s++) {
        stgA[s] = sb + SM_STG0 + s * STG_BYTES;
        stgB[s] = stgA[s] + A_BYTES;
    }

    for (;;) {
        if (tid == 0) jslot = atomicAdd(&g_ticket, 1);
        __syncthreads();
        int j = jslot;
        __syncthreads();
        if (j >= NJOBS) break;

        int t = j >> 7;                 // 128 jobs per step
        int m = (j >> 4) & 7;           // chain (M-block)
        int nb = j & 15;                // N-tile within chain
        int m0 = m * MT, nbase = nb * HT;
        const __half* hin = (t & 1) ? g_h1 : g_h0;
        __half* hout      = (t & 1) ? g_h0 : g_h1;

        // prefetch chunk 0 (x | w) — dependency-free, overlaps the spin below
        load_tile(stgA[0], stgB[0], g_x + (size_t)m0 * (Tn * In) + t * In, Tn * In,
                  g_w, nbase, tid);
        CP_COMMIT();

        // wait for chain m, step t-1 (16 tiles)
        if (t > 0) {
            if (tid == 0)
                while (atomicAdd(&g_done[m * Tn + (t - 1)], 0) < NNB) __nanosleep(32);
            __syncthreads();
        }

        __align__(16) float acc[4][8][4];
#pragma unroll
        for (int mt = 0; mt < 4; mt++)
#pragma unroll
            for (int jj = 0; jj < 8; jj++)
#pragma unroll
                for (int q = 0; q < 4; q++) acc[mt][jj][q] = 0.0f;

#pragma unroll 1
        for (int kc = 0; kc < NCHUNK; kc++) {
            CP_WAIT_0();
            __syncthreads();
            if (kc < NCHUNK - 1)        // chunk kc+1 = h K-range [kc*128, +128)
                load_tile(stgA[(kc + 1) & 1], stgB[(kc + 1) & 1],
                          hin + (size_t)m0 * Hn + kc * KC, Hn,
                          g_w + In + kc * KC, nbase, tid);
            CP_COMMIT();
            mma_chunk(acc, stgA[kc & 1] + (uint32_t)(wm * 64 * ROWB) + aoff,
                           stgB[kc & 1] + (uint32_t)(wn * 16 * ROWB) + boff);
        }

        // epilogue: bias (L1-cached __ldg), LSTM pointwise, L2-coherent h/c
#pragma unroll
        for (int sub = 0; sub < 2; sub++) {
            int hc = wn * 16 + sub * 8 + 2 * tg;
            int n0 = nbase + hc;
            float bi0 = __ldg(b_ih + n0) + __ldg(b_hh + n0);
            float bi1 = __ldg(b_ih + n0 + 1) + __ldg(b_hh + n0 + 1);
            float bf0 = __ldg(b_ih + 1024 + n0) + __ldg(b_hh + 1024 + n0);
            float bf1 = __ldg(b_ih + 1024 + n0 + 1) + __ldg(b_hh + 1024 + n0 + 1);
            float bg0 = __ldg(b_ih + 2048 + n0) + __ldg(b_hh + 2048 + n0);
            float bg1 = __ldg(b_ih + 2048 + n0 + 1) + __ldg(b_hh + 2048 + n0 + 1);
            float bo0 = __ldg(b_ih + 3072 + n0) + __ldg(b_hh + 3072 + n0);
            float bo1 = __ldg(b_ih + 3072 + n0 + 1) + __ldg(b_hh + 3072 + n0 + 1);
#pragma unroll
            for (int mt = 0; mt < 4; mt++) {
                int rbase = m0 + wm * 64 + mt * 16 + g;
#pragma unroll
                for (int rr = 0; rr < 2; rr++) {
                    int r = rbase + rr * 8;
                    size_t off = (size_t)r * Hn + nbase + hc;
                    float2 co = __ldcg((const float2*)(g_c + off));
                    int q0 = rr * 2, q1 = rr * 2 + 1;
                    float i0 = acc[mt][0 + sub][q0] + bi0, i1 = acc[mt][0 + sub][q1] + bi1;
                    float f0 = acc[mt][2 + sub][q0] + bf0, f1 = acc[mt][2 + sub][q1] + bf1;
                    float gg0 = acc[mt][4 + sub][q0] + bg0, gg1 = acc[mt][4 + sub][q1] + bg1;
                    float o0 = acc[mt][6 + sub][q0] + bo0, o1 = acc[mt][6 + sub][q1] + bo1;
                    float cn0 = sigf(f0) * co.x + sigf(i0) * tanhf_(gg0);
                    float cn1 = sigf(f1) * co.y + sigf(i1) * tanhf_(gg1);
                    __stcg((float2*)(g_c + off), make_float2(cn0, cn1));
                    __half2 hv = __floats2half2_rn(sigf(o0) * tanhf_(cn0),
                                                   sigf(o1) * tanhf_(cn1));
                    __stcg((unsigned int*)(hout + off), *(unsigned int*)&hv);
                }
            }
        }

        __threadfence();                // publish h/c before signaling
        __syncthreads();
        if (tid == 0) atomicAdd(&g_done[m * Tn + t], 1);
    }
}

// ---------------- final FC (t=127 odd -> final h in g_h0) ----------------
__global__ void fc_kernel(const float* __restrict__ w_fc, const float* __restrict__ b_fc,
                          float* __restrict__ out) {
    __shared__ float hs[Hn];
    int b = blockIdx.x;
    const __half2* hsrc = (const __half2*)(g_h0 + (size_t)b * Hn);
    for (int i = threadIdx.x; i < Hn / 2; i += 64) {
        float2 v = __half22float2(hsrc[i]);
        hs[2 * i] = v.x; hs[2 * i + 1] = v.y;
    }
    __syncthreads();
    int o = threadIdx.x;
    const float4* wr = (const float4*)(w_fc + (size_t)o * Hn);
    float acc = 0.0f;
#pragma unroll 8
    for (int k = 0; k < Hn / 4; k++) {
        float4 w4 = wr[k];
        float4 h4 = ((const float4*)hs)[k];
        acc += w4.x * h4.x + w4.y * h4.y + w4.z * h4.z + w4.w * h4.w;
    }
    out[b * On + o] = acc + b_fc[o];
}

extern "C" void kernel_launch(void* const* d_in, const int* in_sizes, int n_in,
                              void* d_out, int out_size) {
    (void)in_sizes; (void)n_in; (void)out_size;
    const float* x    = (const float*)d_in[0];
    const float* w_ih = (const float*)d_in[1];
    const float* w_hh = (const float*)d_in[2];
    const float* b_ih = (const float*)d_in[3];
    const float* b_hh = (const float*)d_in[4];
    const float* w_fc = (const float*)d_in[5];
    const float* b_fc = (const float*)d_in[6];
    float* out = (float*)d_out;

    cudaFuncSetAttribute(lstm_ws_kernel,
                         cudaFuncAttributeMaxDynamicSharedMemorySize, SMEM_BYTES);

    init_hc_kernel<<<(Bn * Hn) / 256, 256>>>();
    prep_w_kernel<<<(G4 * K_TOT + 255) / 256, 256>>>(w_ih, w_hh);
    prep_x_kernel<<<(Bn * Tn * In) / 256, 256>>>(x);

    lstm_ws_kernel<<<NBLK, 256, SMEM_BYTES>>>(b_ih, b_hh);

    fc_kernel<<<Bn, 64>>>(w_fc, b_fc, out);
}